// round 12
// baseline (speedup 1.0000x reference)
#include <cuda_runtime.h>
#include <math.h>

// Shapes (hardcoded per reference)
#define V  32
#define B  128
#define P  256
#define J  75
#define S2 25
#define F1 500   // fc1 out
#define F2 200   // fc2 out
#define KX 800   // V*S2

// Scratch (device globals). k-major activations: coalesced across batch.
__device__ float g_z [V*B*J];                        // SLayer output
__device__ __align__(16) float g_xT[KX*B];           // concat acts, [k][b]
__device__ __align__(16) float g_yp[F1*B];           // fc1 pre-BN, [f][b]
__device__ __align__(16) float g_y1[F1*B];           // fc1 post-BN, [f][b]

__device__ __forceinline__ float warpSum(float v) {
    #pragma unroll
    for (int o = 16; o > 0; o >>= 1) v += __shfl_down_sync(0xffffffffu, v, o);
    return v;
}

// ---------------------------------------------------------------------------
// Kernel 1: transform + SLayer. One block per (v, b-pair). blockDim = 160.
// Points stored as float2 in smem: one LDS.64 per point in the exp loop.
__global__ void k_slayer(const float* __restrict__ births, const float* __restrict__ lifetimes,
                         const int* __restrict__ mask, const float* __restrict__ centers,
                         const float* __restrict__ sharpness) {
    int blk = blockIdx.x;           // V * B/2 = 2048
    int v   = blk >> 6;
    int b0  = (blk & 63) << 1;
    __shared__ float2 sq[2][P];
    __shared__ int scnt[2];
    int tid = threadIdx.x;

    if (tid < 64) {
        int w = tid >> 5, lane = tid & 31;
        int base = (v*B + b0 + w) * P;
        int cnt = 0;
        #pragma unroll
        for (int c = 0; c < P/32; ++c) {
            int p = c*32 + lane;
            int mv = mask[base + p];
            float bb = births[base + p], ll = lifetimes[base + p];
            float dd = bb + ll + 0.01f;
            const float inv = 0.70710678118654752440f;
            float x = (bb + dd) * inv;
            float y = (dd - bb) * inv;
            if (y <= 0.1f) y = __logf(y * 10.0f) * 0.1f + 0.1f;
            unsigned bal = __ballot_sync(0xffffffffu, mv != 0);
            if (mv) {
                int pos = cnt + __popc(bal & ((1u << lane) - 1u));
                sq[w][pos] = make_float2(x, y);
            }
            cnt += __popc(bal);
        }
        if (lane == 0) scnt[w] = cnt;
    }
    __syncthreads();

    if (tid < 2*J) {
        int w = (tid >= J);
        int j = tid - w*J;
        int n = scnt[w];
        int cj = (v*J + j) * 2;
        float cx = centers[cj], cy = centers[cj+1];
        float sx = sharpness[cj];   sx *= sx;
        float sy = sharpness[cj+1]; sy *= sy;
        float acc = 0.f;
        const float2* q = sq[w];
        for (int p = 0; p < n; ++p) {
            float2 pt = q[p];
            float dx = pt.x - cx;
            float dy = pt.y - cy;
            float d2 = fmaf(sx*dx, dx, sy*dy*dy);
            acc += __expf(-d2);
        }
        g_z[(v*B + b0 + w)*J + j] = acc;
    }
}

// ---------------------------------------------------------------------------
// Kernel 2: prew + neighbor stack + stage_1(max) + l1 + BN1 + l2 + ReLU.
// One block per v. blockDim = 512. Writes k-major g_xT. (R9 proven, verbatim)
__global__ void k_mid(const float* __restrict__ w1, const float* __restrict__ w2,
                      const float* __restrict__ l1_w, const float* __restrict__ l1_b,
                      const float* __restrict__ bn1_g, const float* __restrict__ bn1_b,
                      const float* __restrict__ l2_w, const float* __restrict__ l2_b) {
    int v = blockIdx.x;
    __shared__ float sW[24];
    __shared__ float hh[64*J];
    __shared__ float su[B*S2];
    __shared__ float sl1[S2*J];
    __shared__ float sl2[S2*S2];
    __shared__ float smean[S2], sscale[S2], sbeta[S2], sb1[S2], sb2[S2];
    int tid = threadIdx.x;

    if (tid < 24) {
        int g = tid/3, c = tid%3;
        float acc = 0.f;
        #pragma unroll 8
        for (int f = 0; f < 32; ++f)
            acc = fmaf(w2[(v*8+g)*32 + f], w1[(v*32+f)*3 + c], acc);
        sW[tid] = acc;
    }
    for (int i = tid; i < S2*J;  i += 512) sl1[i] = l1_w[v*S2*J  + i];
    for (int i = tid; i < S2*S2; i += 512) sl2[i] = l2_w[v*S2*S2 + i];
    if (tid < S2) { sb1[tid] = l1_b[v*S2+tid]; sb2[tid] = l2_b[v*S2+tid]; sbeta[tid] = bn1_b[v*S2+tid]; }
    __syncthreads();

    int vm = (v + V - 1) & (V - 1), vp = (v + 1) & (V - 1);
    for (int half = 0; half < 2; ++half) {
        int bb0 = half * 64;
        for (int i = tid; i < 64*J; i += 512) {
            int bl = i / J, j = i % J, b = bb0 + bl;
            float z0 = g_z[(vm*B + b)*J + j];
            float z1 = g_z[(v *B + b)*J + j];
            float z2 = g_z[(vp*B + b)*J + j];
            float m = -INFINITY;
            #pragma unroll
            for (int g = 0; g < 8; ++g) {
                float s = fmaf(sW[g*3+2], z2, fmaf(sW[g*3+1], z1, sW[g*3]*z0));
                m = fmaxf(m, s);
            }
            hh[i] = m;
        }
        __syncthreads();
        for (int i = tid; i < S2*64; i += 512) {
            int o = i / 64, bl = i % 64;
            float acc = sb1[o];
            const float* hr = &hh[bl*J];
            const float* wr = &sl1[o*J];
            #pragma unroll 5
            for (int j = 0; j < J; ++j) acc = fmaf(hr[j], wr[j], acc);
            su[(bb0 + bl)*S2 + o] = acc;
        }
        __syncthreads();
    }

    int warp = tid >> 5, lane = tid & 31;
    for (int o = warp; o < S2; o += 16) {
        float s = 0.f;
        #pragma unroll
        for (int b = lane; b < B; b += 32) s += su[b*S2 + o];
        s = warpSum(s);
        s = __shfl_sync(0xffffffffu, s, 0);
        float mean = s * (1.f / B);
        float vv = 0.f;
        #pragma unroll
        for (int b = lane; b < B; b += 32) { float d = su[b*S2 + o] - mean; vv = fmaf(d, d, vv); }
        vv = warpSum(vv);
        if (lane == 0) { smean[o] = mean; sscale[o] = bn1_g[v*S2+o] * rsqrtf(vv*(1.f/B) + 1e-5f); }
    }
    __syncthreads();

    for (int i = tid; i < B*S2; i += 512) {
        int o = i % S2;
        su[i] = (su[i] - smean[o]) * sscale[o] + sbeta[o];
    }
    __syncthreads();

    for (int i = tid; i < S2*B; i += 512) {
        int p = i / B, b = i % B;
        float acc = sb2[p];
        const float* ur = &su[b*S2];
        const float* wr = &sl2[p*S2];
        #pragma unroll
        for (int o = 0; o < S2; ++o) acc = fmaf(ur[o], wr[o], acc);
        g_xT[(v*S2 + p)*B + b] = fmaxf(acc, 0.f);
    }
}

// ---------------------------------------------------------------------------
// Kernel 3a: fc1 (800->500) pre-BN, batch-tiled like fc2.
// grid = 63 f-groups x 4 b-tiles = 252 blocks, blockDim = 256.
// Warp w -> feature f0+w, lane l -> batch b0+l. One acc reg/thread.
__global__ void __launch_bounds__(256, 1)
k_fc1nb(const float* __restrict__ fc1_w, const float* __restrict__ fc1_b) {
    __shared__ float sw[8*KX];               // 25.6 KB
    int fg = blockIdx.x >> 2;                // 0..62
    int bt = blockIdx.x & 3;                 // 0..3
    int f0 = fg * 8;
    int b0 = bt * 32;
    int tid = threadIdx.x;
    int w = tid >> 5, lane = tid & 31;

    for (int i = tid; i < 8*KX; i += 256) {
        int f = f0 + i / KX;
        sw[i] = (f < F1) ? fc1_w[f*KX + (i % KX)] : 0.f;
    }
    __syncthreads();

    int f = f0 + w;
    const float* xb = g_xT + b0 + lane;      // [k][b]
    const float* wr = sw + w*KX;
    float acc = (f < F1) ? fc1_b[f] : 0.f;
    #pragma unroll 8
    for (int k = 0; k < KX; ++k)
        acc = fmaf(wr[k], xb[k*B], acc);
    if (f < F1)
        g_yp[f*B + b0 + lane] = acc;
}

// ---------------------------------------------------------------------------
// Kernel 3b: BN2 over batch per feature. grid=125, blockDim=128 (4 warp-features).
__global__ void __launch_bounds__(128, 1)
k_bn2(const float* __restrict__ bn2_g, const float* __restrict__ bn2_b) {
    int w = threadIdx.x >> 5, lane = threadIdx.x & 31;
    int f = blockIdx.x * 4 + w;
    const float* yp = g_yp + f*B;
    float v0 = yp[lane], v1 = yp[lane+32], v2 = yp[lane+64], v3 = yp[lane+96];
    float s = warpSum(v0 + v1 + v2 + v3);
    float mean = __shfl_sync(0xffffffffu, s, 0) * (1.f / B);
    float d0 = v0-mean, d1 = v1-mean, d2 = v2-mean, d3 = v3-mean;
    float vv = warpSum(fmaf(d0,d0, fmaf(d1,d1, fmaf(d2,d2, d3*d3))));
    vv = __shfl_sync(0xffffffffu, vv, 0) * (1.f / B);
    float scale = bn2_g[f] * rsqrtf(vv + 1e-5f);
    float beta  = bn2_b[f];
    float* y = g_y1 + f*B;
    y[lane]    = d0*scale + beta;
    y[lane+32] = d1*scale + beta;
    y[lane+64] = d2*scale + beta;
    y[lane+96] = d3*scale + beta;
}

// ---------------------------------------------------------------------------
// Kernel 4: fc2 (500->200), batch-tiled. grid = 25 o-groups x 4 b-tiles = 100.
// (R11 version — proven winner.)
__global__ void __launch_bounds__(256, 1)
k_fc2(const float* __restrict__ fc2_w, const float* __restrict__ fc2_b,
      float* __restrict__ out) {
    __shared__ float sw[8*F1];               // 16 KB
    int og = blockIdx.x >> 2;
    int bt = blockIdx.x & 3;
    int o0 = og * 8;
    int b0 = bt * 32;
    int tid = threadIdx.x;
    int w = tid >> 5, lane = tid & 31;

    for (int i = tid; i < 8*F1; i += 256) sw[i] = fc2_w[o0*F1 + i];
    __syncthreads();

    const float* yb = g_y1 + b0 + lane;      // [f][b]
    const float* wr = sw + w*F1;
    float acc = fc2_b[o0 + w];
    #pragma unroll 10
    for (int f = 0; f < F1; ++f)
        acc = fmaf(wr[f], yb[f*B], acc);
    out[(b0 + lane)*F2 + o0 + w] = acc;
}

// ---------------------------------------------------------------------------
extern "C" void kernel_launch(void* const* d_in, const int* in_sizes, int n_in,
                              void* d_out, int out_size) {
    const float* births    = (const float*)d_in[0];
    const float* lifetimes = (const float*)d_in[1];
    const int*   mask      = (const int*)  d_in[2];
    const float* centers   = (const float*)d_in[3];
    const float* sharpness = (const float*)d_in[4];
    const float* w1        = (const float*)d_in[5];
    const float* w2        = (const float*)d_in[6];
    const float* l1_w      = (const float*)d_in[7];
    const float* l1_b      = (const float*)d_in[8];
    const float* bn1_g     = (const float*)d_in[9];
    const float* bn1_b     = (const float*)d_in[10];
    const float* l2_w      = (const float*)d_in[11];
    const float* l2_b      = (const float*)d_in[12];
    const float* fc1_w     = (const float*)d_in[13];
    const float* fc1_b     = (const float*)d_in[14];
    const float* bn2_g     = (const float*)d_in[15];
    const float* bn2_b     = (const float*)d_in[16];
    const float* fc2_w     = (const float*)d_in[17];
    const float* fc2_b     = (const float*)d_in[18];
    float* out = (float*)d_out;

    k_slayer<<<V*B/2, 160>>>(births, lifetimes, mask, centers, sharpness);
    k_mid   <<<V, 512>>>(w1, w2, l1_w, l1_b, bn1_g, bn1_b, l2_w, l2_b);
    k_fc1nb <<<63*4, 256>>>(fc1_w, fc1_b);
    k_bn2   <<<F1/4, 128>>>(bn2_g, bn2_b);
    k_fc2   <<<100, 256>>>(fc2_w, fc2_b, out);
}

// round 13
// speedup vs baseline: 1.2793x; 1.2793x over previous
#include <cuda_runtime.h>
#include <math.h>

// Shapes (hardcoded per reference)
#define V  32
#define B  128
#define P  256
#define J  75
#define S2 25
#define F1 500   // fc1 out
#define F2 200   // fc2 out
#define KX 800   // V*S2

// Scratch (device globals). k-major activations: coalesced across batch.
__device__ float g_z [V*B*J];                        // SLayer output
__device__ __align__(16) float g_xT[KX*B];           // concat acts, [k][b]
__device__ __align__(16) float g_y1[F1*B];           // fc1 post-BN, [f][b]

__device__ __forceinline__ float warpSum(float v) {
    #pragma unroll
    for (int o = 16; o > 0; o >>= 1) v += __shfl_down_sync(0xffffffffu, v, o);
    return v;
}

// ---------------------------------------------------------------------------
// Kernel 1: transform + SLayer. One block per (v, b-pair). blockDim = 160.
// (R9/62.0us version, verbatim)
__global__ void k_slayer(const float* __restrict__ births, const float* __restrict__ lifetimes,
                         const int* __restrict__ mask, const float* __restrict__ centers,
                         const float* __restrict__ sharpness) {
    int blk = blockIdx.x;           // V * B/2 = 2048
    int v   = blk >> 6;
    int b0  = (blk & 63) << 1;
    __shared__ float sqx[2][P], sqy[2][P];
    __shared__ int scnt[2];
    int tid = threadIdx.x;

    if (tid < 64) {
        int w = tid >> 5, lane = tid & 31;
        int base = (v*B + b0 + w) * P;
        int cnt = 0;
        #pragma unroll
        for (int c = 0; c < P/32; ++c) {
            int p = c*32 + lane;
            int mv = mask[base + p];
            float bb = births[base + p], ll = lifetimes[base + p];
            float dd = bb + ll + 0.01f;
            const float inv = 0.70710678118654752440f;
            float x = (bb + dd) * inv;
            float y = (dd - bb) * inv;
            if (y <= 0.1f) y = __logf(y * 10.0f) * 0.1f + 0.1f;
            unsigned bal = __ballot_sync(0xffffffffu, mv != 0);
            if (mv) {
                int pos = cnt + __popc(bal & ((1u << lane) - 1u));
                sqx[w][pos] = x; sqy[w][pos] = y;
            }
            cnt += __popc(bal);
        }
        if (lane == 0) scnt[w] = cnt;
    }
    __syncthreads();

    if (tid < 2*J) {
        int w = (tid >= J);
        int j = tid - w*J;
        int n = scnt[w];
        int cj = (v*J + j) * 2;
        float cx = centers[cj], cy = centers[cj+1];
        float sx = sharpness[cj];   sx *= sx;
        float sy = sharpness[cj+1]; sy *= sy;
        float acc = 0.f;
        for (int p = 0; p < n; ++p) {
            float dx = sqx[w][p] - cx;
            float dy = sqy[w][p] - cy;
            float d2 = fmaf(sx*dx, dx, sy*dy*dy);
            acc += __expf(-d2);
        }
        g_z[(v*B + b0 + w)*J + j] = acc;
    }
}

// ---------------------------------------------------------------------------
// Kernel 2: prew + neighbor stack + stage_1(max) + l1 + BN1 + l2 + ReLU.
// One block per v. blockDim = 512. (R9/62.0us version, verbatim)
__global__ void k_mid(const float* __restrict__ w1, const float* __restrict__ w2,
                      const float* __restrict__ l1_w, const float* __restrict__ l1_b,
                      const float* __restrict__ bn1_g, const float* __restrict__ bn1_b,
                      const float* __restrict__ l2_w, const float* __restrict__ l2_b) {
    int v = blockIdx.x;
    __shared__ float sW[24];
    __shared__ float hh[64*J];
    __shared__ float su[B*S2];
    __shared__ float sl1[S2*J];
    __shared__ float sl2[S2*S2];
    __shared__ float smean[S2], sscale[S2], sbeta[S2], sb1[S2], sb2[S2];
    int tid = threadIdx.x;

    if (tid < 24) {
        int g = tid/3, c = tid%3;
        float acc = 0.f;
        #pragma unroll 8
        for (int f = 0; f < 32; ++f)
            acc = fmaf(w2[(v*8+g)*32 + f], w1[(v*32+f)*3 + c], acc);
        sW[tid] = acc;
    }
    for (int i = tid; i < S2*J;  i += 512) sl1[i] = l1_w[v*S2*J  + i];
    for (int i = tid; i < S2*S2; i += 512) sl2[i] = l2_w[v*S2*S2 + i];
    if (tid < S2) { sb1[tid] = l1_b[v*S2+tid]; sb2[tid] = l2_b[v*S2+tid]; sbeta[tid] = bn1_b[v*S2+tid]; }
    __syncthreads();

    int vm = (v + V - 1) & (V - 1), vp = (v + 1) & (V - 1);
    for (int half = 0; half < 2; ++half) {
        int bb0 = half * 64;
        for (int i = tid; i < 64*J; i += 512) {
            int bl = i / J, j = i % J, b = bb0 + bl;
            float z0 = g_z[(vm*B + b)*J + j];
            float z1 = g_z[(v *B + b)*J + j];
            float z2 = g_z[(vp*B + b)*J + j];
            float m = -INFINITY;
            #pragma unroll
            for (int g = 0; g < 8; ++g) {
                float s = fmaf(sW[g*3+2], z2, fmaf(sW[g*3+1], z1, sW[g*3]*z0));
                m = fmaxf(m, s);
            }
            hh[i] = m;
        }
        __syncthreads();
        for (int i = tid; i < S2*64; i += 512) {
            int o = i / 64, bl = i % 64;
            float acc = sb1[o];
            const float* hr = &hh[bl*J];
            const float* wr = &sl1[o*J];
            #pragma unroll 5
            for (int j = 0; j < J; ++j) acc = fmaf(hr[j], wr[j], acc);
            su[(bb0 + bl)*S2 + o] = acc;
        }
        __syncthreads();
    }

    int warp = tid >> 5, lane = tid & 31;
    for (int o = warp; o < S2; o += 16) {
        float s = 0.f;
        #pragma unroll
        for (int b = lane; b < B; b += 32) s += su[b*S2 + o];
        s = warpSum(s);
        s = __shfl_sync(0xffffffffu, s, 0);
        float mean = s * (1.f / B);
        float vv = 0.f;
        #pragma unroll
        for (int b = lane; b < B; b += 32) { float d = su[b*S2 + o] - mean; vv = fmaf(d, d, vv); }
        vv = warpSum(vv);
        if (lane == 0) { smean[o] = mean; sscale[o] = bn1_g[v*S2+o] * rsqrtf(vv*(1.f/B) + 1e-5f); }
    }
    __syncthreads();

    for (int i = tid; i < B*S2; i += 512) {
        int o = i % S2;
        su[i] = (su[i] - smean[o]) * sscale[o] + sbeta[o];
    }
    __syncthreads();

    for (int i = tid; i < S2*B; i += 512) {
        int p = i / B, b = i % B;
        float acc = sb2[p];
        const float* ur = &su[b*S2];
        const float* wr = &sl2[p*S2];
        #pragma unroll
        for (int o = 0; o < S2; ++o) acc = fmaf(ur[o], wr[o], acc);
        g_xT[(v*S2 + p)*B + b] = fmaxf(acc, 0.f);
    }
}

// ---------------------------------------------------------------------------
// Kernel 3: fc1 (800->500) + BN2. grid=100, blockDim=512 (16 warps).
// (R9/62.0us version, verbatim)
#define FPB 5
__global__ void __launch_bounds__(512, 1)
k_fc1(const float* __restrict__ fc1_w, const float* __restrict__ fc1_b,
      const float* __restrict__ bn2_g, const float* __restrict__ bn2_b) {
    __shared__ float sw[FPB*KX];            // 16 KB
    __shared__ float part[8*FPB*B];         // 20 KB
    __shared__ float smean[FPB], sscale[FPB];
    int f0 = blockIdx.x * FPB;
    int tid = threadIdx.x;
    int w = tid >> 5, lane = tid & 31;

    for (int i = tid; i < FPB*KX; i += 512) sw[i] = fc1_w[f0*KX + i];
    __syncthreads();

    float acc[FPB][4];
    #pragma unroll
    for (int ff = 0; ff < FPB; ++ff) {
        float bv = (w == 0) ? fc1_b[f0+ff] : 0.f;
        acc[ff][0] = bv; acc[ff][1] = bv; acc[ff][2] = bv; acc[ff][3] = bv;
    }
    const float4* x4 = reinterpret_cast<const float4*>(g_xT);  // [k][b/4]
    int k0 = w * 50;
    #pragma unroll 8
    for (int k = k0; k < k0 + 50; ++k) {
        float4 xv = x4[k*32 + lane];
        #pragma unroll
        for (int ff = 0; ff < FPB; ++ff) {
            float wv = sw[ff*KX + k];
            acc[ff][0] = fmaf(wv, xv.x, acc[ff][0]);
            acc[ff][1] = fmaf(wv, xv.y, acc[ff][1]);
            acc[ff][2] = fmaf(wv, xv.z, acc[ff][2]);
            acc[ff][3] = fmaf(wv, xv.w, acc[ff][3]);
        }
    }
    if (w < 8) {
        #pragma unroll
        for (int ff = 0; ff < FPB; ++ff)
            #pragma unroll
            for (int u = 0; u < 4; ++u)
                part[(w*FPB + ff)*B + 4*lane + u] = acc[ff][u];
    }
    __syncthreads();
    if (w >= 8) {
        #pragma unroll
        for (int ff = 0; ff < FPB; ++ff)
            #pragma unroll
            for (int u = 0; u < 4; ++u)
                part[((w-8)*FPB + ff)*B + 4*lane + u] += acc[ff][u];
    }
    __syncthreads();
    for (int i = tid; i < FPB*B; i += 512) {
        float s = part[i];
        #pragma unroll
        for (int ks = 1; ks < 8; ++ks) s += part[ks*FPB*B + i];
        part[i] = s;
    }
    __syncthreads();

    if (w < FPB) {
        float s = 0.f;
        #pragma unroll
        for (int b = lane; b < B; b += 32) s += part[w*B + b];
        s = warpSum(s);
        s = __shfl_sync(0xffffffffu, s, 0);
        float mean = s * (1.f / B);
        float vv = 0.f;
        #pragma unroll
        for (int b = lane; b < B; b += 32) { float d = part[w*B + b] - mean; vv = fmaf(d, d, vv); }
        vv = warpSum(vv);
        if (lane == 0) { smean[w] = mean; sscale[w] = bn2_g[f0+w] * rsqrtf(vv*(1.f/B) + 1e-5f); }
    }
    __syncthreads();

    for (int i = tid; i < FPB*B; i += 512) {
        int ff = i / B, b = i % B;
        g_y1[(f0+ff)*B + b] = (part[i] - smean[ff]) * sscale[ff] + bn2_b[f0+ff];
    }
}

// ---------------------------------------------------------------------------
// Kernel 4: fc2 (500->200), batch-tiled (R11 version — measured winner).
// grid = 25 o-groups x 4 b-tiles = 100, blockDim = 256.
// Warp w -> output o0+w, lane l -> batch b0+l. One acc reg/thread;
// each y-load is one coalesced 128B line, shared across warps via L1.
__global__ void __launch_bounds__(256, 1)
k_fc2(const float* __restrict__ fc2_w, const float* __restrict__ fc2_b,
      float* __restrict__ out) {
    __shared__ float sw[8*F1];               // 16 KB
    int og = blockIdx.x >> 2;
    int bt = blockIdx.x & 3;
    int o0 = og * 8;
    int b0 = bt * 32;
    int tid = threadIdx.x;
    int w = tid >> 5, lane = tid & 31;

    for (int i = tid; i < 8*F1; i += 256) sw[i] = fc2_w[o0*F1 + i];
    __syncthreads();

    const float* yb = g_y1 + b0 + lane;      // [f][b]
    const float* wr = sw + w*F1;
    float acc = fc2_b[o0 + w];
    #pragma unroll 10
    for (int f = 0; f < F1; ++f)
        acc = fmaf(wr[f], yb[f*B], acc);
    out[(b0 + lane)*F2 + o0 + w] = acc;
}

// ---------------------------------------------------------------------------
extern "C" void kernel_launch(void* const* d_in, const int* in_sizes, int n_in,
                              void* d_out, int out_size) {
    const float* births    = (const float*)d_in[0];
    const float* lifetimes = (const float*)d_in[1];
    const int*   mask      = (const int*)  d_in[2];
    const float* centers   = (const float*)d_in[3];
    const float* sharpness = (const float*)d_in[4];
    const float* w1        = (const float*)d_in[5];
    const float* w2        = (const float*)d_in[6];
    const float* l1_w      = (const float*)d_in[7];
    const float* l1_b      = (const float*)d_in[8];
    const float* bn1_g     = (const float*)d_in[9];
    const float* bn1_b     = (const float*)d_in[10];
    const float* l2_w      = (const float*)d_in[11];
    const float* l2_b      = (const float*)d_in[12];
    const float* fc1_w     = (const float*)d_in[13];
    const float* fc1_b     = (const float*)d_in[14];
    const float* bn2_g     = (const float*)d_in[15];
    const float* bn2_b     = (const float*)d_in[16];
    const float* fc2_w     = (const float*)d_in[17];
    const float* fc2_b     = (const float*)d_in[18];
    float* out = (float*)d_out;

    k_slayer<<<V*B/2, 160>>>(births, lifetimes, mask, centers, sharpness);
    k_mid   <<<V, 512>>>(w1, w2, l1_w, l1_b, bn1_g, bn1_b, l2_w, l2_b);
    k_fc1   <<<F1/FPB, 512>>>(fc1_w, fc1_b, bn2_g, bn2_b);
    k_fc2   <<<100, 256>>>(fc2_w, fc2_b, out);
}

// round 14
// speedup vs baseline: 1.5863x; 1.2400x over previous
#include <cuda_runtime.h>
#include <math.h>

// Shapes (hardcoded per reference)
#define V  32
#define B  128
#define P  256
#define J  75
#define S2 25
#define F1 500   // fc1 out
#define F2 200   // fc2 out
#define KX 800   // V*S2

// Scratch (device globals). k-major activations: coalesced across batch.
__device__ float g_z [V*B*J];                        // SLayer output
__device__ __align__(16) float g_xT[KX*B];           // concat acts, [k][b]
__device__ __align__(16) float g_y1[F1*B];           // fc1 post-BN, [f][b]

__device__ __forceinline__ float warpSum(float v) {
    #pragma unroll
    for (int o = 16; o > 0; o >>= 1) v += __shfl_down_sync(0xffffffffu, v, o);
    return v;
}

// ---------------------------------------------------------------------------
// Kernel 1: transform + SLayer. One block per (v, b-pair). blockDim = 160.
// R9 structure; points stored as float2 (one LDS.64 per point in exp loop).
__global__ void k_slayer(const float* __restrict__ births, const float* __restrict__ lifetimes,
                         const int* __restrict__ mask, const float* __restrict__ centers,
                         const float* __restrict__ sharpness) {
    int blk = blockIdx.x;           // V * B/2 = 2048
    int v   = blk >> 6;
    int b0  = (blk & 63) << 1;
    __shared__ float2 sq[2][P];
    __shared__ int scnt[2];
    int tid = threadIdx.x;

    if (tid < 64) {
        int w = tid >> 5, lane = tid & 31;
        int base = (v*B + b0 + w) * P;
        int cnt = 0;
        #pragma unroll
        for (int c = 0; c < P/32; ++c) {
            int p = c*32 + lane;
            int mv = mask[base + p];
            float bb = births[base + p], ll = lifetimes[base + p];
            float dd = bb + ll + 0.01f;
            const float inv = 0.70710678118654752440f;
            float x = (bb + dd) * inv;
            float y = (dd - bb) * inv;
            if (y <= 0.1f) y = __logf(y * 10.0f) * 0.1f + 0.1f;
            unsigned bal = __ballot_sync(0xffffffffu, mv != 0);
            if (mv) {
                int pos = cnt + __popc(bal & ((1u << lane) - 1u));
                sq[w][pos] = make_float2(x, y);
            }
            cnt += __popc(bal);
        }
        if (lane == 0) scnt[w] = cnt;
    }
    __syncthreads();

    if (tid < 2*J) {
        int w = (tid >= J);
        int j = tid - w*J;
        int n = scnt[w];
        int cj = (v*J + j) * 2;
        float cx = centers[cj], cy = centers[cj+1];
        float sx = sharpness[cj];   sx *= sx;
        float sy = sharpness[cj+1]; sy *= sy;
        float acc = 0.f;
        const float2* q = sq[w];
        for (int p = 0; p < n; ++p) {
            float2 pt = q[p];
            float dx = pt.x - cx;
            float dy = pt.y - cy;
            float d2 = fmaf(sx*dx, dx, sy*dy*dy);
            acc += __expf(-d2);
        }
        g_z[(v*B + b0 + w)*J + j] = acc;
    }
}

// ---------------------------------------------------------------------------
// Kernel 2: prew + neighbor stack + stage_1(max) + l1 + BN1 + l2 + ReLU.
// One block per v. blockDim = 512. (R9/62.0us version, verbatim)
__global__ void k_mid(const float* __restrict__ w1, const float* __restrict__ w2,
                      const float* __restrict__ l1_w, const float* __restrict__ l1_b,
                      const float* __restrict__ bn1_g, const float* __restrict__ bn1_b,
                      const float* __restrict__ l2_w, const float* __restrict__ l2_b) {
    int v = blockIdx.x;
    __shared__ float sW[24];
    __shared__ float hh[64*J];
    __shared__ float su[B*S2];
    __shared__ float sl1[S2*J];
    __shared__ float sl2[S2*S2];
    __shared__ float smean[S2], sscale[S2], sbeta[S2], sb1[S2], sb2[S2];
    int tid = threadIdx.x;

    if (tid < 24) {
        int g = tid/3, c = tid%3;
        float acc = 0.f;
        #pragma unroll 8
        for (int f = 0; f < 32; ++f)
            acc = fmaf(w2[(v*8+g)*32 + f], w1[(v*32+f)*3 + c], acc);
        sW[tid] = acc;
    }
    for (int i = tid; i < S2*J;  i += 512) sl1[i] = l1_w[v*S2*J  + i];
    for (int i = tid; i < S2*S2; i += 512) sl2[i] = l2_w[v*S2*S2 + i];
    if (tid < S2) { sb1[tid] = l1_b[v*S2+tid]; sb2[tid] = l2_b[v*S2+tid]; sbeta[tid] = bn1_b[v*S2+tid]; }
    __syncthreads();

    int vm = (v + V - 1) & (V - 1), vp = (v + 1) & (V - 1);
    for (int half = 0; half < 2; ++half) {
        int bb0 = half * 64;
        for (int i = tid; i < 64*J; i += 512) {
            int bl = i / J, j = i % J, b = bb0 + bl;
            float z0 = g_z[(vm*B + b)*J + j];
            float z1 = g_z[(v *B + b)*J + j];
            float z2 = g_z[(vp*B + b)*J + j];
            float m = -INFINITY;
            #pragma unroll
            for (int g = 0; g < 8; ++g) {
                float s = fmaf(sW[g*3+2], z2, fmaf(sW[g*3+1], z1, sW[g*3]*z0));
                m = fmaxf(m, s);
            }
            hh[i] = m;
        }
        __syncthreads();
        for (int i = tid; i < S2*64; i += 512) {
            int o = i / 64, bl = i % 64;
            float acc = sb1[o];
            const float* hr = &hh[bl*J];
            const float* wr = &sl1[o*J];
            #pragma unroll 5
            for (int j = 0; j < J; ++j) acc = fmaf(hr[j], wr[j], acc);
            su[(bb0 + bl)*S2 + o] = acc;
        }
        __syncthreads();
    }

    int warp = tid >> 5, lane = tid & 31;
    for (int o = warp; o < S2; o += 16) {
        float s = 0.f;
        #pragma unroll
        for (int b = lane; b < B; b += 32) s += su[b*S2 + o];
        s = warpSum(s);
        s = __shfl_sync(0xffffffffu, s, 0);
        float mean = s * (1.f / B);
        float vv = 0.f;
        #pragma unroll
        for (int b = lane; b < B; b += 32) { float d = su[b*S2 + o] - mean; vv = fmaf(d, d, vv); }
        vv = warpSum(vv);
        if (lane == 0) { smean[o] = mean; sscale[o] = bn1_g[v*S2+o] * rsqrtf(vv*(1.f/B) + 1e-5f); }
    }
    __syncthreads();

    for (int i = tid; i < B*S2; i += 512) {
        int o = i % S2;
        su[i] = (su[i] - smean[o]) * sscale[o] + sbeta[o];
    }
    __syncthreads();

    for (int i = tid; i < S2*B; i += 512) {
        int p = i / B, b = i % B;
        float acc = sb2[p];
        const float* ur = &su[b*S2];
        const float* wr = &sl2[p*S2];
        #pragma unroll
        for (int o = 0; o < S2; ++o) acc = fmaf(ur[o], wr[o], acc);
        g_xT[(v*S2 + p)*B + b] = fmaxf(acc, 0.f);
    }
}

// ---------------------------------------------------------------------------
// Kernel 3: fc1 (800->500) + BN2. R9 structure; FPB 5->4, grid 100->125.
#define FPB 4
__global__ void __launch_bounds__(512, 1)
k_fc1(const float* __restrict__ fc1_w, const float* __restrict__ fc1_b,
      const float* __restrict__ bn2_g, const float* __restrict__ bn2_b) {
    __shared__ float sw[FPB*KX];            // 12.8 KB
    __shared__ float part[8*FPB*B];         // 16 KB
    __shared__ float smean[FPB], sscale[FPB];
    int f0 = blockIdx.x * FPB;
    int tid = threadIdx.x;
    int w = tid >> 5, lane = tid & 31;

    for (int i = tid; i < FPB*KX; i += 512) sw[i] = fc1_w[f0*KX + i];
    __syncthreads();

    float acc[FPB][4];
    #pragma unroll
    for (int ff = 0; ff < FPB; ++ff) {
        float bv = (w == 0) ? fc1_b[f0+ff] : 0.f;
        acc[ff][0] = bv; acc[ff][1] = bv; acc[ff][2] = bv; acc[ff][3] = bv;
    }
    const float4* x4 = reinterpret_cast<const float4*>(g_xT);  // [k][b/4]
    int k0 = w * 50;
    #pragma unroll 8
    for (int k = k0; k < k0 + 50; ++k) {
        float4 xv = x4[k*32 + lane];
        #pragma unroll
        for (int ff = 0; ff < FPB; ++ff) {
            float wv = sw[ff*KX + k];
            acc[ff][0] = fmaf(wv, xv.x, acc[ff][0]);
            acc[ff][1] = fmaf(wv, xv.y, acc[ff][1]);
            acc[ff][2] = fmaf(wv, xv.z, acc[ff][2]);
            acc[ff][3] = fmaf(wv, xv.w, acc[ff][3]);
        }
    }
    if (w < 8) {
        #pragma unroll
        for (int ff = 0; ff < FPB; ++ff)
            #pragma unroll
            for (int u = 0; u < 4; ++u)
                part[(w*FPB + ff)*B + 4*lane + u] = acc[ff][u];
    }
    __syncthreads();
    if (w >= 8) {
        #pragma unroll
        for (int ff = 0; ff < FPB; ++ff)
            #pragma unroll
            for (int u = 0; u < 4; ++u)
                part[((w-8)*FPB + ff)*B + 4*lane + u] += acc[ff][u];
    }
    __syncthreads();
    for (int i = tid; i < FPB*B; i += 512) {
        float s = part[i];
        #pragma unroll
        for (int ks = 1; ks < 8; ++ks) s += part[ks*FPB*B + i];
        part[i] = s;
    }
    __syncthreads();

    if (w < FPB) {
        float s = 0.f;
        #pragma unroll
        for (int b = lane; b < B; b += 32) s += part[w*B + b];
        s = warpSum(s);
        s = __shfl_sync(0xffffffffu, s, 0);
        float mean = s * (1.f / B);
        float vv = 0.f;
        #pragma unroll
        for (int b = lane; b < B; b += 32) { float d = part[w*B + b] - mean; vv = fmaf(d, d, vv); }
        vv = warpSum(vv);
        if (lane == 0) { smean[w] = mean; sscale[w] = bn2_g[f0+w] * rsqrtf(vv*(1.f/B) + 1e-5f); }
    }
    __syncthreads();

    for (int i = tid; i < FPB*B; i += 512) {
        int ff = i / B, b = i % B;
        g_y1[(f0+ff)*B + b] = (part[i] - smean[ff]) * sscale[ff] + bn2_b[f0+ff];
    }
}

// ---------------------------------------------------------------------------
// Kernel 4: fc2 (500->200). grid=100, blockDim=512 (16 warps).
// (R9/62.0us version, verbatim)
#define OPB 2
__global__ void __launch_bounds__(512, 1)
k_fc2(const float* __restrict__ fc2_w, const float* __restrict__ fc2_b,
      float* __restrict__ out) {
    __shared__ float sw[OPB*F1];            // 4 KB
    __shared__ float part[8*OPB*B];         // 8 KB
    int o0 = blockIdx.x * OPB;
    int tid = threadIdx.x;
    int w = tid >> 5, lane = tid & 31;

    for (int i = tid; i < OPB*F1; i += 512) sw[i] = fc2_w[o0*F1 + i];
    __syncthreads();

    float a0[4], a1[4];
    {
        float b0 = (w == 0) ? fc2_b[o0]   : 0.f;
        float b1 = (w == 0) ? fc2_b[o0+1] : 0.f;
        a0[0]=b0; a0[1]=b0; a0[2]=b0; a0[3]=b0;
        a1[0]=b1; a1[1]=b1; a1[2]=b1; a1[3]=b1;
    }
    const float4* y4 = reinterpret_cast<const float4*>(g_y1);  // [f][b/4]
    int fs = (w * F1) / 16, fe = ((w + 1) * F1) / 16;
    #pragma unroll 8
    for (int f = fs; f < fe; ++f) {
        float4 yv = y4[f*32 + lane];
        float w0 = sw[f], w1 = sw[F1 + f];
        a0[0] = fmaf(w0, yv.x, a0[0]); a1[0] = fmaf(w1, yv.x, a1[0]);
        a0[1] = fmaf(w0, yv.y, a0[1]); a1[1] = fmaf(w1, yv.y, a1[1]);
        a0[2] = fmaf(w0, yv.z, a0[2]); a1[2] = fmaf(w1, yv.z, a1[2]);
        a0[3] = fmaf(w0, yv.w, a0[3]); a1[3] = fmaf(w1, yv.w, a1[3]);
    }
    if (w < 8) {
        #pragma unroll
        for (int u = 0; u < 4; ++u) {
            part[(w*OPB + 0)*B + 4*lane + u] = a0[u];
            part[(w*OPB + 1)*B + 4*lane + u] = a1[u];
        }
    }
    __syncthreads();
    if (w >= 8) {
        #pragma unroll
        for (int u = 0; u < 4; ++u) {
            part[((w-8)*OPB + 0)*B + 4*lane + u] += a0[u];
            part[((w-8)*OPB + 1)*B + 4*lane + u] += a1[u];
        }
    }
    __syncthreads();
    for (int i = tid; i < OPB*B; i += 512) {
        float s = part[i];
        #pragma unroll
        for (int ks = 1; ks < 8; ++ks) s += part[ks*OPB*B + i];
        int oo = i / B, b = i % B;
        out[b*F2 + o0 + oo] = s;
    }
}

// ---------------------------------------------------------------------------
extern "C" void kernel_launch(void* const* d_in, const int* in_sizes, int n_in,
                              void* d_out, int out_size) {
    const float* births    = (const float*)d_in[0];
    const float* lifetimes = (const float*)d_in[1];
    const int*   mask      = (const int*)  d_in[2];
    const float* centers   = (const float*)d_in[3];
    const float* sharpness = (const float*)d_in[4];
    const float* w1        = (const float*)d_in[5];
    const float* w2        = (const float*)d_in[6];
    const float* l1_w      = (const float*)d_in[7];
    const float* l1_b      = (const float*)d_in[8];
    const float* bn1_g     = (const float*)d_in[9];
    const float* bn1_b     = (const float*)d_in[10];
    const float* l2_w      = (const float*)d_in[11];
    const float* l2_b      = (const float*)d_in[12];
    const float* fc1_w     = (const float*)d_in[13];
    const float* fc1_b     = (const float*)d_in[14];
    const float* bn2_g     = (const float*)d_in[15];
    const float* bn2_b     = (const float*)d_in[16];
    const float* fc2_w     = (const float*)d_in[17];
    const float* fc2_b     = (const float*)d_in[18];
    float* out = (float*)d_out;

    k_slayer<<<V*B/2, 160>>>(births, lifetimes, mask, centers, sharpness);
    k_mid   <<<V, 512>>>(w1, w2, l1_w, l1_b, bn1_g, bn1_b, l2_w, l2_b);
    k_fc1   <<<F1/FPB, 512>>>(fc1_w, fc1_b, bn2_g, bn2_b);
    k_fc2   <<<F2/OPB, 512>>>(fc2_w, fc2_b, out);
}